// round 16
// baseline (speedup 1.0000x reference)
#include <cuda_runtime.h>
#include <math.h>

#define BB 4
#define NN 2048
#define NBINS 10
#define NP 5
#define BN (BB*NN)
#define NTILES 8     // gt-row tiles of 256 rows
#define MSPLIT 32    // pred-col tiles of 64 cols
#define FINF 3.0e38f

// ---------------- scratch (device globals; no allocations allowed) -----------
__device__ float g_pm1[MSPLIT][BN], g_pm2[MSPLIT][BN];
__device__ int   g_pi1[MSPLIT][BN], g_pi2[MSPLIT][BN];
__device__ float g_colmin[NTILES][BN];
__device__ float g_part[32][8];   // per-block partials: cd,ca,off,g2p,adds,succ,sbce

__device__ __forceinline__ float softplusf(float x){
    return log1pf(expf(-fabsf(x))) + fmaxf(x, 0.0f);
}

// Build the 15-float control-point vector + squared norm for one grasp frame.
__device__ __forceinline__ void build_frame(
    const float b0, const float b1, const float b2,
    const float a0, const float a1, const float a2,
    const float p0, const float p1, const float p2,
    const float* __restrict__ head10, const float* __restrict__ bv,
    const float* __restrict__ cpt, float* v /*16*/)
{
    // first-occurrence argmax (matches jnp.argmax)
    float best=-FINF; int ib=0;
    #pragma unroll
    for (int i=0;i<NBINS;i++){
        const float h = head10[i];
        if (h > best){ best=h; ib=i; }
    }
    const float t = bv[ib];

    const float c0 = a1*b2 - a2*b1;
    const float c1 = a2*b0 - a0*b2;
    const float c2 = a0*b1 - a1*b0;
    const float t0 = p0 + 0.5f*t*b0, t1 = p1 + 0.5f*t*b1, t2 = p2 + 0.5f*t*b2;

    float n2 = 0.f;
    #pragma unroll
    for (int p=0;p<NP;p++){
        const float cx=cpt[p*3+0], cy=cpt[p*3+1], cz=cpt[p*3+2];
        const float x = cx*b0 + cy*c0 + cz*a0 + t0;
        const float y = cx*b1 + cy*c1 + cz*a1 + t1;
        const float z = cx*b2 + cy*c2 + cz*a2 + t2;
        v[p*3+0]=x; v[p*3+1]=y; v[p*3+2]=z;
        n2 += x*x + y*y + z*z;
    }
    v[15]=n2;
}

// ---------------- Kernel B: fused transform + tiled NxN reductions ------------
// Each thread owns 2 gt rows (row, row+128). Block's pred tile is 64 columns
// (transform computed in-kernel by threads 0..63). Sym control points are the
// permutation [0,1,3,2,4] of gt control points: dotS reuses 3 of 5 segment
// dots and the sym squared-norm equals gt's.
__global__ void __launch_bounds__(128) kB(
    const float* __restrict__ gd_, const float* __restrict__ ad_,
    const float* __restrict__ oh_, const float* __restrict__ pp_,
    const float* __restrict__ dl_, const float* __restrict__ ol_,
    const float* __restrict__ succ_, const float* __restrict__ al_,
    const float* __restrict__ bv, const float* __restrict__ cpt)
{
    __shared__ float4 s4PR[64*4];        // pred tile (64 cols), 4 KB
    __shared__ float  scand[128][65];    // candidate tile, 33.3 KB
    __shared__ float  scolpart[128];

    const int ntile = blockIdx.x;    // 0..7  (gt rows base = ntile*256)
    const int b     = blockIdx.y;    // 0..3
    const int split = blockIdx.z;    // 0..31 (pred cols base = split*64)
    const int tid   = threadIdx.x;   // 0..127
    const int row0  = ntile*256 + tid;
    const int gA    = b*NN + row0;
    const int gB    = gA + 128;
    const int mbase = split*64;

    // ---- stage pred tile: threads 0..63 transform one column each ----
    if (tid < 64){
        const int pidx = b*NN + mbase + tid;
        float vp[16];
        build_frame(gd_[pidx*3+0], gd_[pidx*3+1], gd_[pidx*3+2],
                    ad_[pidx*3+0], ad_[pidx*3+1], ad_[pidx*3+2],
                    pp_[pidx*3+0], pp_[pidx*3+1], pp_[pidx*3+2],
                    oh_ + pidx*NBINS, bv, cpt, vp);
        #pragma unroll
        for (int q=0;q<4;q++)
            s4PR[tid*4+q] = make_float4(vp[q*4+0], vp[q*4+1], vp[q*4+2], vp[q*4+3]);
    }

    // ---- own 2 gt rows (transform in-kernel) ----
    float ra[16], rb[16];
    build_frame(dl_[gA*3+0], dl_[gA*3+1], dl_[gA*3+2],
                al_[gA*3+0], al_[gA*3+1], al_[gA*3+2],
                pp_[gA*3+0], pp_[gA*3+1], pp_[gA*3+2],
                ol_ + gA*NBINS, bv, cpt, ra);
    build_frame(dl_[gB*3+0], dl_[gB*3+1], dl_[gB*3+2],
                al_[gB*3+0], al_[gB*3+1], al_[gB*3+2],
                pp_[gB*3+0], pp_[gB*3+1], pp_[gB*3+2],
                ol_ + gB*NBINS, bv, cpt, rb);
    const bool posA = succ_[gA] > 0.5f;
    const bool posB = succ_[gB] > 0.5f;
    __syncthreads();

    float m1a=FINF,m2a=FINF, m1b=FINF,m2b=FINF;
    int i1a=0,i2a=0, i1b=0,i2b=0;

    #pragma unroll 4
    for (int j=0;j<64;j++){
        const float4 c0=s4PR[j*4+0], c1=s4PR[j*4+1], c2=s4PR[j*4+2], c3=s4PR[j*4+3];

        // ---- row A ----
        float A0 = ra[0]*c0.x + ra[1]*c0.y + ra[2]*c0.z;
        float A1 = ra[3]*c0.w + ra[4]*c1.x + ra[5]*c1.y;
        float A2 = ra[6]*c1.z + ra[7]*c1.w + ra[8]*c2.x;
        float A3 = ra[9]*c2.y + ra[10]*c2.z + ra[11]*c2.w;
        float A4 = ra[12]*c3.x + ra[13]*c3.y + ra[14]*c3.z;
        float P2 = ra[9]*c1.z + ra[10]*c1.w + ra[11]*c2.x;   // gt seg3 . pred seg2
        float P3 = ra[6]*c2.y + ra[7]*c2.z + ra[8]*c2.w;     // gt seg2 . pred seg3
        float s014 = A0 + A1 + A4;
        float dotG = s014 + A2 + A3;
        float dotS = s014 + P2 + P3;
        float base = ra[15] + c3.w;
        float dgA0 = fmaxf(fmaf(-2.0f, dotG, base), 0.0f);
        float dgB0 = fmaxf(fmaf(-2.0f, dotS, base), 0.0f);
        if (dgA0 < m1a){ m1a=dgA0; i1a=mbase+j; }
        if (dgB0 < m2a){ m2a=dgB0; i2a=mbase+j; }

        // ---- row B ----
        float C0 = rb[0]*c0.x + rb[1]*c0.y + rb[2]*c0.z;
        float C1 = rb[3]*c0.w + rb[4]*c1.x + rb[5]*c1.y;
        float C2 = rb[6]*c1.z + rb[7]*c1.w + rb[8]*c2.x;
        float C3 = rb[9]*c2.y + rb[10]*c2.z + rb[11]*c2.w;
        float C4 = rb[12]*c3.x + rb[13]*c3.y + rb[14]*c3.z;
        float Q2 = rb[9]*c1.z + rb[10]*c1.w + rb[11]*c2.x;
        float Q3 = rb[6]*c2.y + rb[7]*c2.z + rb[8]*c2.w;
        float t014 = C0 + C1 + C4;
        float dotG2 = t014 + C2 + C3;
        float dotS2 = t014 + Q2 + Q3;
        float base2 = rb[15] + c3.w;
        float dgA1 = fmaxf(fmaf(-2.0f, dotG2, base2), 0.0f);
        float dgB1 = fmaxf(fmaf(-2.0f, dotS2, base2), 0.0f);
        if (dgA1 < m1b){ m1b=dgA1; i1b=mbase+j; }
        if (dgB1 < m2b){ m2b=dgB1; i2b=mbase+j; }

        const float candA = posA ? fminf(dgA0,dgB0) : FINF;
        const float candB = posB ? fminf(dgA1,dgB1) : FINF;
        scand[tid][j] = fminf(candA, candB);
    }
    __syncthreads();

    // column-min: 2 threads per column over 128 thread-rows
    {
        const int col  = tid & 63;
        const int half = tid >> 6;
        float cm = scand[half*64][col];
        #pragma unroll 8
        for (int i=1;i<64;i++) cm = fminf(cm, scand[half*64+i][col]);
        scolpart[tid] = cm;
    }
    __syncthreads();
    if (tid < 64)
        g_colmin[ntile][b*NN + mbase + tid] =
            fminf(scolpart[tid], scolpart[tid+64]);

    g_pm1[split][gA]=m1a; g_pi1[split][gA]=i1a;
    g_pm2[split][gA]=m2a; g_pi2[split][gA]=i2a;
    g_pm1[split][gB]=m1b; g_pi1[split][gB]=i1b;
    g_pm2[split][gB]=m2b; g_pi2[split][gB]=i2b;
}

// ---------------- Kernel C1: per-point losses + epilogue reductions -----------
__global__ void kC1(const float* __restrict__ bsp, const float* __restrict__ succ_,
                    const float* __restrict__ gd_, const float* __restrict__ ad_,
                    const float* __restrict__ oh_, const float* __restrict__ bsh_,
                    const float* __restrict__ dl_, const float* __restrict__ ol_,
                    const float* __restrict__ al_, const float* __restrict__ bw)
{
    __shared__ float red[256];
    const int tid = threadIdx.x;
    const int g   = blockIdx.x*256 + tid;   // 32 blocks x 256 = 8192
    const int b   = g >> 11;

    const float succ = succ_[g];
    const float gd0=gd_[g*3+0], gd1=gd_[g*3+1], gd2=gd_[g*3+2];
    const float ad0=ad_[g*3+0], ad1=ad_[g*3+1], ad2=ad_[g*3+2];
    const float dl0=dl_[g*3+0], dl1=dl_[g*3+1], dl2=dl_[g*3+2];
    const float al0=al_[g*3+0], al1=al_[g*3+1], al2=al_[g*3+2];

    // dir cosine
    const float cd = (1.0f - (dl0*gd0+dl1*gd1+dl2*gd2))*succ;
    // approach cosine (orthogonalized label)
    const float proj = gd0*al0+gd1*al1+gd2*al2;
    const float o0=al0-proj*gd0, o1=al1-proj*gd1, o2=al2-proj*gd2;
    const float nrm = sqrtf(o0*o0+o1*o1+o2*o2);
    const float inv = 1.0f/fmaxf(nrm,1e-12f);
    const float ca = (1.0f - (o0*ad0+o1*ad1+o2*ad2)*inv)*succ;
    // offset bce
    float off=0.f;
    #pragma unroll
    for (int i=0;i<NBINS;i++){
        const float ohv = oh_[g*NBINS+i];
        const float olv = ol_[g*NBINS+i];
        const float bce = olv*softplusf(-ohv) + (1.0f-olv)*softplusf(ohv);
        off += bw[i]*bce;
    }
    off = off*(1.0f/NBINS)*succ;
    // score bce
    const float hh = bsh_[g];
    const float sbce = succ*softplusf(-hh) + (1.0f-succ)*softplusf(hh);

    // pred->gt best: merge NTILES column partials (min, order-free); always finite
    float best = g_colmin[0][g];
    #pragma unroll
    for (int t=1;t<NTILES;t++) best = fminf(best, g_colmin[t][g]);
    const float adds = bsp[g]*sqrtf(best);   // gate applied per-batch in kC2

    // gt->pred: ordered merge of MSPLIT partials (first-occurrence argmin)
    float m1=g_pm1[0][g]; int i1=g_pi1[0][g];
    float m2=g_pm2[0][g]; int i2=g_pi2[0][g];
    #pragma unroll
    for (int s=1;s<MSPLIT;s++){
        const float a=g_pm1[s][g]; if (a<m1){m1=a;i1=g_pi1[s][g];}
        const float c=g_pm2[s][g]; if (c<m2){m2=c;i2=g_pi2[s][g];}
    }
    const int idcs = (m2<m1)? i2 : i1;
    const float conf = bsp[b*NN+idcs];
    const float g2p = conf * fminf(m1,m2) * succ;

    float vals[7] = {cd, ca, off, g2p, adds, succ, sbce};
    #pragma unroll
    for (int q=0;q<7;q++){
        red[tid]=vals[q]; __syncthreads();
        for (int s=128;s>0;s>>=1){ if(tid<s) red[tid]+=red[tid+s]; __syncthreads(); }
        if (tid==0) g_part[blockIdx.x][q]=red[0];
        __syncthreads();
    }
}

// ---------------- Kernel C2: tiny deterministic merge -------------------------
__global__ void kC2(float* __restrict__ out)
{
    __shared__ float sp[32][8];
    const int t = threadIdx.x;
    if (t < 32){
        #pragma unroll
        for (int q=0;q<7;q++) sp[t][q]=g_part[t][q];
    }
    __syncthreads();
    if (t==0){
        float tdir=0.f,tapp=0.f,toff=0.f,tg2p=0.f,tadds=0.f,tsb=0.f;
        for (int b=0;b<BB;b++){
            float s[7]={0,0,0,0,0,0,0};
            for (int k=0;k<8;k++){           // 8 blocks per batch, fixed order
                #pragma unroll
                for (int q=0;q<7;q++) s[q]+=sp[b*8+k][q];
            }
            const float piv  = fmaxf(s[5],1.0f);
            const float gate = fminf(s[5],1.0f);
            tdir += s[0]/piv; tapp += s[1]/piv; toff += s[2]/piv;
            tg2p += s[3]/piv; tadds += gate*s[4]; tsb += s[6];
        }
        out[0] = tdir/(float)BB + tsb/(float)BN + toff/(float)BB + tapp/(float)BB
               + 10.0f*(tadds/(float)BN) + tg2p/(float)BB;
    }
}

// ---------------- launcher ---------------------------------------------------
extern "C" void kernel_launch(void* const* d_in, const int* in_sizes, int n_in,
                              void* d_out, int out_size)
{
    const float* gd   = (const float*)d_in[0];
    const float* ad   = (const float*)d_in[1];
    const float* oh   = (const float*)d_in[2];
    const float* pp   = (const float*)d_in[3];
    const float* bsp  = (const float*)d_in[4];
    const float* bsh  = (const float*)d_in[5];
    const float* dl   = (const float*)d_in[6];
    const float* ol   = (const float*)d_in[7];
    const float* succ = (const float*)d_in[8];
    const float* al   = (const float*)d_in[9];
    const float* bv   = (const float*)d_in[10];
    const float* bw   = (const float*)d_in[11];
    const float* cpt  = (const float*)d_in[12];
    float* out = (float*)d_out;

    kB<<<dim3(NTILES, BB, MSPLIT), 128>>>(gd, ad, oh, pp, dl, ol, succ, al, bv, cpt);
    kC1<<<32, 256>>>(bsp, succ, gd, ad, oh, bsh, dl, ol, al, bw);
    kC2<<<1, 32>>>(out);
}

// round 17
// speedup vs baseline: 1.0469x; 1.0469x over previous
#include <cuda_runtime.h>
#include <math.h>

#define BB 4
#define NN 2048
#define NBINS 10
#define NP 5
#define BN (BB*NN)
#define NTILES 8     // gt-row tiles of 256 rows
#define MSPLIT 32    // pred-col tiles of 64 cols
#define NCBLK 64     // kC1 blocks (16 per batch)
#define FINF 3.0e38f

// ---------------- scratch (device globals; no allocations allowed) -----------
__device__ float g_pm1[MSPLIT][BN], g_pm2[MSPLIT][BN];
__device__ int   g_pi1[MSPLIT][BN], g_pi2[MSPLIT][BN];
__device__ float g_colmin[NTILES][BN];
__device__ float g_part[NCBLK][8];  // per-block partials: cd,ca,off,g2p,adds,succ,sbce

__device__ __forceinline__ float softplusf(float x){
    return log1pf(expf(-fabsf(x))) + fmaxf(x, 0.0f);
}

// Build the 15-float control-point vector + squared norm for one grasp frame.
__device__ __forceinline__ void build_frame(
    const float b0, const float b1, const float b2,
    const float a0, const float a1, const float a2,
    const float p0, const float p1, const float p2,
    const float* __restrict__ head10, const float* __restrict__ bv,
    const float* __restrict__ cpt, float* v /*16*/)
{
    // first-occurrence argmax (matches jnp.argmax)
    float best=-FINF; int ib=0;
    #pragma unroll
    for (int i=0;i<NBINS;i++){
        const float h = head10[i];
        if (h > best){ best=h; ib=i; }
    }
    const float t = bv[ib];

    const float c0 = a1*b2 - a2*b1;
    const float c1 = a2*b0 - a0*b2;
    const float c2 = a0*b1 - a1*b0;
    const float t0 = p0 + 0.5f*t*b0, t1 = p1 + 0.5f*t*b1, t2 = p2 + 0.5f*t*b2;

    float n2 = 0.f;
    #pragma unroll
    for (int p=0;p<NP;p++){
        const float cx=cpt[p*3+0], cy=cpt[p*3+1], cz=cpt[p*3+2];
        const float x = cx*b0 + cy*c0 + cz*a0 + t0;
        const float y = cx*b1 + cy*c1 + cz*a1 + t1;
        const float z = cx*b2 + cy*c2 + cz*a2 + t2;
        v[p*3+0]=x; v[p*3+1]=y; v[p*3+2]=z;
        n2 += x*x + y*y + z*z;
    }
    v[15]=n2;
}

// ---------------- Kernel B: fused transform + tiled NxN reductions ------------
// (unchanged from the 33.6us-measured version)
__global__ void __launch_bounds__(128) kB(
    const float* __restrict__ gd_, const float* __restrict__ ad_,
    const float* __restrict__ oh_, const float* __restrict__ pp_,
    const float* __restrict__ dl_, const float* __restrict__ ol_,
    const float* __restrict__ succ_, const float* __restrict__ al_,
    const float* __restrict__ bv, const float* __restrict__ cpt)
{
    __shared__ float4 s4PR[64*4];        // pred tile (64 cols), 4 KB
    __shared__ float  scand[128][65];    // candidate tile, 33.3 KB
    __shared__ float  scolpart[128];

    const int ntile = blockIdx.x;    // 0..7  (gt rows base = ntile*256)
    const int b     = blockIdx.y;    // 0..3
    const int split = blockIdx.z;    // 0..31 (pred cols base = split*64)
    const int tid   = threadIdx.x;   // 0..127
    const int row0  = ntile*256 + tid;
    const int gA    = b*NN + row0;
    const int gB    = gA + 128;
    const int mbase = split*64;

    // ---- stage pred tile: threads 0..63 transform one column each ----
    if (tid < 64){
        const int pidx = b*NN + mbase + tid;
        float vp[16];
        build_frame(gd_[pidx*3+0], gd_[pidx*3+1], gd_[pidx*3+2],
                    ad_[pidx*3+0], ad_[pidx*3+1], ad_[pidx*3+2],
                    pp_[pidx*3+0], pp_[pidx*3+1], pp_[pidx*3+2],
                    oh_ + pidx*NBINS, bv, cpt, vp);
        #pragma unroll
        for (int q=0;q<4;q++)
            s4PR[tid*4+q] = make_float4(vp[q*4+0], vp[q*4+1], vp[q*4+2], vp[q*4+3]);
    }

    // ---- own 2 gt rows (transform in-kernel) ----
    float ra[16], rb[16];
    build_frame(dl_[gA*3+0], dl_[gA*3+1], dl_[gA*3+2],
                al_[gA*3+0], al_[gA*3+1], al_[gA*3+2],
                pp_[gA*3+0], pp_[gA*3+1], pp_[gA*3+2],
                ol_ + gA*NBINS, bv, cpt, ra);
    build_frame(dl_[gB*3+0], dl_[gB*3+1], dl_[gB*3+2],
                al_[gB*3+0], al_[gB*3+1], al_[gB*3+2],
                pp_[gB*3+0], pp_[gB*3+1], pp_[gB*3+2],
                ol_ + gB*NBINS, bv, cpt, rb);
    const bool posA = succ_[gA] > 0.5f;
    const bool posB = succ_[gB] > 0.5f;
    __syncthreads();

    float m1a=FINF,m2a=FINF, m1b=FINF,m2b=FINF;
    int i1a=0,i2a=0, i1b=0,i2b=0;

    #pragma unroll 4
    for (int j=0;j<64;j++){
        const float4 c0=s4PR[j*4+0], c1=s4PR[j*4+1], c2=s4PR[j*4+2], c3=s4PR[j*4+3];

        // ---- row A ----
        float A0 = ra[0]*c0.x + ra[1]*c0.y + ra[2]*c0.z;
        float A1 = ra[3]*c0.w + ra[4]*c1.x + ra[5]*c1.y;
        float A2 = ra[6]*c1.z + ra[7]*c1.w + ra[8]*c2.x;
        float A3 = ra[9]*c2.y + ra[10]*c2.z + ra[11]*c2.w;
        float A4 = ra[12]*c3.x + ra[13]*c3.y + ra[14]*c3.z;
        float P2 = ra[9]*c1.z + ra[10]*c1.w + ra[11]*c2.x;   // gt seg3 . pred seg2
        float P3 = ra[6]*c2.y + ra[7]*c2.z + ra[8]*c2.w;     // gt seg2 . pred seg3
        float s014 = A0 + A1 + A4;
        float dotG = s014 + A2 + A3;
        float dotS = s014 + P2 + P3;
        float base = ra[15] + c3.w;
        float dgA0 = fmaxf(fmaf(-2.0f, dotG, base), 0.0f);
        float dgB0 = fmaxf(fmaf(-2.0f, dotS, base), 0.0f);
        if (dgA0 < m1a){ m1a=dgA0; i1a=mbase+j; }
        if (dgB0 < m2a){ m2a=dgB0; i2a=mbase+j; }

        // ---- row B ----
        float C0 = rb[0]*c0.x + rb[1]*c0.y + rb[2]*c0.z;
        float C1 = rb[3]*c0.w + rb[4]*c1.x + rb[5]*c1.y;
        float C2 = rb[6]*c1.z + rb[7]*c1.w + rb[8]*c2.x;
        float C3 = rb[9]*c2.y + rb[10]*c2.z + rb[11]*c2.w;
        float C4 = rb[12]*c3.x + rb[13]*c3.y + rb[14]*c3.z;
        float Q2 = rb[9]*c1.z + rb[10]*c1.w + rb[11]*c2.x;
        float Q3 = rb[6]*c2.y + rb[7]*c2.z + rb[8]*c2.w;
        float t014 = C0 + C1 + C4;
        float dotG2 = t014 + C2 + C3;
        float dotS2 = t014 + Q2 + Q3;
        float base2 = rb[15] + c3.w;
        float dgA1 = fmaxf(fmaf(-2.0f, dotG2, base2), 0.0f);
        float dgB1 = fmaxf(fmaf(-2.0f, dotS2, base2), 0.0f);
        if (dgA1 < m1b){ m1b=dgA1; i1b=mbase+j; }
        if (dgB1 < m2b){ m2b=dgB1; i2b=mbase+j; }

        const float candA = posA ? fminf(dgA0,dgB0) : FINF;
        const float candB = posB ? fminf(dgA1,dgB1) : FINF;
        scand[tid][j] = fminf(candA, candB);
    }
    __syncthreads();

    // column-min: 2 threads per column over 128 thread-rows
    {
        const int col  = tid & 63;
        const int half = tid >> 6;
        float cm = scand[half*64][col];
        #pragma unroll 8
        for (int i=1;i<64;i++) cm = fminf(cm, scand[half*64+i][col]);
        scolpart[tid] = cm;
    }
    __syncthreads();
    if (tid < 64)
        g_colmin[ntile][b*NN + mbase + tid] =
            fminf(scolpart[tid], scolpart[tid+64]);

    g_pm1[split][gA]=m1a; g_pi1[split][gA]=i1a;
    g_pm2[split][gA]=m2a; g_pi2[split][gA]=i2a;
    g_pm1[split][gB]=m1b; g_pi1[split][gB]=i1b;
    g_pm2[split][gB]=m2b; g_pi2[split][gB]=i2b;
}

// ---------------- Kernel C1: per-point losses + shuffle-reduced partials ------
__global__ void __launch_bounds__(128) kC1(
    const float* __restrict__ bsp, const float* __restrict__ succ_,
    const float* __restrict__ gd_, const float* __restrict__ ad_,
    const float* __restrict__ oh_, const float* __restrict__ bsh_,
    const float* __restrict__ dl_, const float* __restrict__ ol_,
    const float* __restrict__ al_, const float* __restrict__ bw)
{
    __shared__ float swp[4][8];             // per-warp partials
    const int tid = threadIdx.x;            // 0..127
    const int g   = blockIdx.x*128 + tid;   // 64 blocks x 128 = 8192
    const int b   = g >> 11;

    const float succ = succ_[g];
    const float gd0=gd_[g*3+0], gd1=gd_[g*3+1], gd2=gd_[g*3+2];
    const float ad0=ad_[g*3+0], ad1=ad_[g*3+1], ad2=ad_[g*3+2];
    const float dl0=dl_[g*3+0], dl1=dl_[g*3+1], dl2=dl_[g*3+2];
    const float al0=al_[g*3+0], al1=al_[g*3+1], al2=al_[g*3+2];

    // dir cosine
    const float cd = (1.0f - (dl0*gd0+dl1*gd1+dl2*gd2))*succ;
    // approach cosine (orthogonalized label)
    const float proj = gd0*al0+gd1*al1+gd2*al2;
    const float o0=al0-proj*gd0, o1=al1-proj*gd1, o2=al2-proj*gd2;
    const float nrm = sqrtf(o0*o0+o1*o1+o2*o2);
    const float inv = 1.0f/fmaxf(nrm,1e-12f);
    const float ca = (1.0f - (o0*ad0+o1*ad1+o2*ad2)*inv)*succ;
    // offset bce
    float off=0.f;
    #pragma unroll
    for (int i=0;i<NBINS;i++){
        const float ohv = oh_[g*NBINS+i];
        const float olv = ol_[g*NBINS+i];
        const float bce = olv*softplusf(-ohv) + (1.0f-olv)*softplusf(ohv);
        off += bw[i]*bce;
    }
    off = off*(1.0f/NBINS)*succ;
    // score bce
    const float hh = bsh_[g];
    const float sbce = succ*softplusf(-hh) + (1.0f-succ)*softplusf(hh);

    // pred->gt best: merge NTILES column partials (min, order-free); always finite
    float best = g_colmin[0][g];
    #pragma unroll
    for (int t=1;t<NTILES;t++) best = fminf(best, g_colmin[t][g]);
    const float adds = bsp[g]*sqrtf(best);   // gate applied per-batch in kC2

    // gt->pred: ordered merge of MSPLIT partials (first-occurrence argmin)
    float m1=g_pm1[0][g]; int i1=g_pi1[0][g];
    float m2=g_pm2[0][g]; int i2=g_pi2[0][g];
    #pragma unroll
    for (int s=1;s<MSPLIT;s++){
        const float a=g_pm1[s][g]; if (a<m1){m1=a;i1=g_pi1[s][g];}
        const float c=g_pm2[s][g]; if (c<m2){m2=c;i2=g_pi2[s][g];}
    }
    const int idcs = (m2<m1)? i2 : i1;
    const float conf = bsp[b*NN+idcs];
    const float g2p = conf * fminf(m1,m2) * succ;

    // warp-shuffle reduce 7 values (fixed order -> deterministic)
    float vals[7] = {cd, ca, off, g2p, adds, succ, sbce};
    const int wid = tid >> 5, lid = tid & 31;
    #pragma unroll
    for (int q=0;q<7;q++){
        float v = vals[q];
        #pragma unroll
        for (int o=16;o>0;o>>=1) v += __shfl_down_sync(0xFFFFFFFFu, v, o);
        if (lid==0) swp[wid][q]=v;
    }
    __syncthreads();
    if (tid < 7)
        g_part[blockIdx.x][tid] = ((swp[0][tid]+swp[1][tid])+swp[2][tid])+swp[3][tid];
}

// ---------------- Kernel C2: parallel deterministic merge ---------------------
__global__ void kC2(float* __restrict__ out)
{
    __shared__ float sq[7][4];   // [quantity][batch]
    const int t = threadIdx.x;   // 0..63
    if (t < 28){
        const int q = t >> 2, b = t & 3;    // 16 kC1 blocks per batch
        float s = 0.f;
        #pragma unroll
        for (int k=0;k<16;k++) s += g_part[b*16+k][q];   // fixed order
        sq[q][b] = s;
    }
    __syncthreads();
    if (t==0){
        float tdir=0.f,tapp=0.f,toff=0.f,tg2p=0.f,tadds=0.f,tsb=0.f;
        for (int b=0;b<BB;b++){
            const float piv  = fmaxf(sq[5][b],1.0f);
            const float gate = fminf(sq[5][b],1.0f);
            tdir += sq[0][b]/piv; tapp += sq[1][b]/piv; toff += sq[2][b]/piv;
            tg2p += sq[3][b]/piv; tadds += gate*sq[4][b]; tsb += sq[6][b];
        }
        out[0] = tdir/(float)BB + tsb/(float)BN + toff/(float)BB + tapp/(float)BB
               + 10.0f*(tadds/(float)BN) + tg2p/(float)BB;
    }
}

// ---------------- launcher ---------------------------------------------------
extern "C" void kernel_launch(void* const* d_in, const int* in_sizes, int n_in,
                              void* d_out, int out_size)
{
    const float* gd   = (const float*)d_in[0];
    const float* ad   = (const float*)d_in[1];
    const float* oh   = (const float*)d_in[2];
    const float* pp   = (const float*)d_in[3];
    const float* bsp  = (const float*)d_in[4];
    const float* bsh  = (const float*)d_in[5];
    const float* dl   = (const float*)d_in[6];
    const float* ol   = (const float*)d_in[7];
    const float* succ = (const float*)d_in[8];
    const float* al   = (const float*)d_in[9];
    const float* bv   = (const float*)d_in[10];
    const float* bw   = (const float*)d_in[11];
    const float* cpt  = (const float*)d_in[12];
    float* out = (float*)d_out;

    kB<<<dim3(NTILES, BB, MSPLIT), 128>>>(gd, ad, oh, pp, dl, ol, succ, al, bv, cpt);
    kC1<<<NCBLK, 128>>>(bsp, succ, gd, ad, oh, bsh, dl, ol, al, bw);
    kC2<<<1, 64>>>(out);
}